// round 5
// baseline (speedup 1.0000x reference)
#include <cuda_runtime.h>
#include <math.h>

// Problem constants
#define BB 4
#define TT 4096
#define CC 1024
#define WW 64
#define EE 16
#define DD 64
#define NBLK 64          // T/W
#define MROWS 256        // B*N
#define MT 16384         // B*T
#define NEGV -1e9f
#define SPLITK 16

// ---------------- scratch (device globals; no allocation) ----------------
__device__ float g_Wqkv[3072 * 1024];      // repacked [j=sel*1024+e*64+d][c]  (NT layout)
__device__ float g_Ot[1024 * 1024];        // o_proj transposed: [c][e*64+d]
__device__ float g_simnorm[32];            // 0..15: g_sim col rnorm, 16..31: f_sim
__device__ float g_compP[SPLITK * MROWS * CC]; // split-K partials
__device__ float g_comp[MROWS * CC];
__device__ float g_bmask[MROWS];
__device__ float g_rw[MT * EE];
__device__ float g_qkv[(size_t)MT * 3072]; // [row][ q(1024) | k(1024) | v(1024) ], cols (e,d)
__device__ float g_wctx[(size_t)MT * 1024];// rw-weighted attention context, (B,T,E*D)

// ---------------- prep kernels ----------------
__global__ void repack_qkv_kernel(const float* __restrict__ qp, const float* __restrict__ kp,
                                  const float* __restrict__ vp) {
    int idx = blockIdx.x * blockDim.x + threadIdx.x;   // over 3072*1024
    if (idx >= 3072 * 1024) return;
    int j = idx >> 10, c = idx & 1023;
    int sel = j >> 10;
    int jj = j & 1023;
    int e = jj >> 6, d = jj & 63;
    const float* src = (sel == 0) ? qp : (sel == 1) ? kp : vp;
    // proj shape (E, C, D): [e*C*D + c*D + d]
    g_Wqkv[idx] = src[(e << 16) + (c << 6) + d];
}

__global__ void repack_o_kernel(const float* __restrict__ op) {
    int idx = blockIdx.x * blockDim.x + threadIdx.x;   // over 1024*1024
    if (idx >= 1024 * 1024) return;
    int c = idx >> 10, kk = idx & 1023;
    g_Ot[idx] = op[kk * 1024 + c];   // o_proj flat (E*D, C)
}

__global__ void simnorm_kernel(const float* __restrict__ gsim, const float* __restrict__ fsim) {
    int w = threadIdx.x >> 5;   // 0..31
    int lane = threadIdx.x & 31;
    int e = w & 15;
    const float* s = (w < 16) ? gsim : fsim;
    float acc = 0.f;
    for (int c = lane; c < CC; c += 32) {
        float v = s[c * EE + e];
        acc += v * v;
    }
    #pragma unroll
    for (int o = 16; o; o >>= 1) acc += __shfl_xor_sync(0xffffffffu, acc, o);
    if (lane == 0) g_simnorm[w] = rsqrtf(acc + 1e-12f);
}

// ---------------- generic NT SGEMM: C[M,N] = A(MxK,row) * Bt(NxK,row)^T ----------------
// BM=BN=128, BK=8, 256 threads, 8x8 microtile.
// Double-buffered smem + register prefetch: one __syncthreads per K-iteration.
// EPI 0: C[r*N+c] = acc.   EPI 1: C += blockIdx.z*M*N (split-K partial buffers).
template <int EPI>
__global__ void __launch_bounds__(256) sgemm_nt(const float* __restrict__ A,
                                                const float* __restrict__ Bt,
                                                float* __restrict__ C,
                                                int M, int N, int lda, int ldb, int kLen) {
    __shared__ float As[2][8][128];
    __shared__ float Bs[2][8][128];
    const int tid = threadIdx.x;
    const int lr = tid >> 1;           // 0..127
    const int lc = (tid & 1) * 4;      // 0 or 4
    const int tx = tid & 15, ty = tid >> 4;
    const size_t kBase = (size_t)blockIdx.z * kLen;
    const float* Ab = A + (size_t)(blockIdx.y * 128 + lr) * lda + kBase + lc;
    const float* Bb = Bt + (size_t)(blockIdx.x * 128 + lr) * ldb + kBase + lc;

    float acc[8][8];
    #pragma unroll
    for (int i = 0; i < 8; i++)
        #pragma unroll
        for (int j = 0; j < 8; j++) acc[i][j] = 0.f;

    // prologue: load slab 0 into buffer 0
    {
        float4 av = *(const float4*)(Ab);
        float4 bv = *(const float4*)(Bb);
        As[0][lc + 0][lr] = av.x; As[0][lc + 1][lr] = av.y;
        As[0][lc + 2][lr] = av.z; As[0][lc + 3][lr] = av.w;
        Bs[0][lc + 0][lr] = bv.x; Bs[0][lc + 1][lr] = bv.y;
        Bs[0][lc + 2][lr] = bv.z; Bs[0][lc + 3][lr] = bv.w;
    }
    __syncthreads();

    int cur = 0;
    for (int k0 = 0; k0 < kLen; k0 += 8) {
        const bool has_next = (k0 + 8 < kLen);
        float4 av, bv;
        if (has_next) {
            av = *(const float4*)(Ab + k0 + 8);
            bv = *(const float4*)(Bb + k0 + 8);
        }
        // compute on buffer `cur` (gmem loads above are in flight)
        #pragma unroll
        for (int kk = 0; kk < 8; kk++) {
            float a[8], b[8];
            #pragma unroll
            for (int i = 0; i < 8; i++) a[i] = As[cur][kk][ty * 8 + i];
            #pragma unroll
            for (int j = 0; j < 8; j++) b[j] = Bs[cur][kk][tx * 8 + j];
            #pragma unroll
            for (int i = 0; i < 8; i++)
                #pragma unroll
                for (int j = 0; j < 8; j++) acc[i][j] += a[i] * b[j];
        }
        if (has_next) {
            int nxt = cur ^ 1;
            // safe: last reads of `nxt` finished before the previous iteration's barrier
            As[nxt][lc + 0][lr] = av.x; As[nxt][lc + 1][lr] = av.y;
            As[nxt][lc + 2][lr] = av.z; As[nxt][lc + 3][lr] = av.w;
            Bs[nxt][lc + 0][lr] = bv.x; Bs[nxt][lc + 1][lr] = bv.y;
            Bs[nxt][lc + 2][lr] = bv.z; Bs[nxt][lc + 3][lr] = bv.w;
            __syncthreads();
            cur = nxt;
        }
    }

    float* Cb = C;
    if (EPI == 1) Cb += (size_t)blockIdx.z * M * N;
    #pragma unroll
    for (int i = 0; i < 8; i++) {
        int r = blockIdx.y * 128 + ty * 8 + i;
        #pragma unroll
        for (int j = 0; j < 8; j++) {
            int c = blockIdx.x * 128 + tx * 8 + j;
            Cb[(size_t)r * N + c] = acc[i][j];
        }
    }
}

// ---------------- compress epilogue: sum split-K partials + bias + relu ----------------
__global__ void compress_epilogue_kernel(const float* __restrict__ cb) {
    int i = blockIdx.x * blockDim.x + threadIdx.x;  // over 256*1024
    if (i >= MROWS * CC) return;
    float s = cb[i & 1023];
    #pragma unroll
    for (int z = 0; z < SPLITK; z++) s += g_compP[z * (MROWS * CC) + i];
    g_comp[i] = fmaxf(s, 0.f);
}

// ---------------- gating (exact replica of reference semantics, E=16) ----------------
__device__ __forceinline__ void gating16(const float* logits, float* probs) {
    float gated[16];
    bool act[16];
    int nact = 0;
    #pragma unroll
    for (int e = 0; e < 16; e++) {
        gated[e] = fmaxf(logits[e], 0.f);
        act[e] = gated[e] > 0.f;
        nact += act[e] ? 1 : 0;
    }
    if (nact == 0) {
        int i1 = 0; float b1 = logits[0];
        #pragma unroll
        for (int e = 1; e < 16; e++) if (logits[e] > b1) { b1 = logits[e]; i1 = e; }
        int i2 = -1; float b2 = -3.4e38f;
        #pragma unroll
        for (int e = 0; e < 16; e++) if (e != i1 && logits[e] > b2) { b2 = logits[e]; i2 = e; }
        #pragma unroll
        for (int e = 0; e < 16; e++) act[e] = (e == i1) || (e == i2);
    }
    float m = -3.4e38f;
    float msk[16];
    #pragma unroll
    for (int e = 0; e < 16; e++) {
        msk[e] = act[e] ? gated[e] : NEGV;
        m = fmaxf(m, msk[e]);
    }
    float s = 0.f;
    #pragma unroll
    for (int e = 0; e < 16; e++) { float x = expf(msk[e] - m); probs[e] = x; s += x; }
    float inv = 1.f / s;
    #pragma unroll
    for (int e = 0; e < 16; e++) probs[e] *= inv;
}

__device__ __forceinline__ float sigmoidf_(float x) { return 1.f / (1.f + expf(-x)); }

// one warp per comp row (256 rows) -> block mask
__global__ void g_gate_kernel(const float* __restrict__ gsim, const float* __restrict__ ggates,
                              const float* __restrict__ thr) {
    int row = blockIdx.x;
    int lane = threadIdx.x;
    const float* x = g_comp + row * CC;
    float ss = 0.f;
    float acc[16];
    #pragma unroll
    for (int e = 0; e < 16; e++) acc[e] = 0.f;
    for (int c = lane; c < CC; c += 32) {
        float xv = x[c];
        ss += xv * xv;
        const float* sr = gsim + c * EE;
        #pragma unroll
        for (int e = 0; e < 16; e++) acc[e] += xv * sr[e];
    }
    #pragma unroll
    for (int o = 16; o; o >>= 1) {
        ss += __shfl_xor_sync(0xffffffffu, ss, o);
        #pragma unroll
        for (int e = 0; e < 16; e++) acc[e] += __shfl_xor_sync(0xffffffffu, acc[e], o);
    }
    if (lane == 0) {
        float rx = rsqrtf(ss + 1e-12f);
        float logits[16], probs[16];
        #pragma unroll
        for (int e = 0; e < 16; e++)
            logits[e] = acc[e] * rx * g_simnorm[e] - sigmoidf_(ggates[e]);
        gating16(logits, probs);
        float imp = 0.f;
        #pragma unroll
        for (int e = 0; e < 16; e++) imp = fmaxf(imp, probs[e]);
        g_bmask[row] = (imp - thr[0] > 0.f) ? 1.f : 0.f;
    }
}

// one warp per hidden-state row (16384 rows) -> rw = f_probs * tok_mask
__global__ void f_gate_kernel(const float* __restrict__ hs, const float* __restrict__ fsim,
                              const float* __restrict__ fgates) {
    int row = blockIdx.x * 8 + (threadIdx.x >> 5);
    int lane = threadIdx.x & 31;
    const float* x = hs + (size_t)row * CC;
    float ss = 0.f;
    float acc[16];
    #pragma unroll
    for (int e = 0; e < 16; e++) acc[e] = 0.f;
    for (int c = lane; c < CC; c += 32) {
        float xv = x[c];
        ss += xv * xv;
        const float* sr = fsim + c * EE;
        #pragma unroll
        for (int e = 0; e < 16; e++) acc[e] += xv * sr[e];
    }
    #pragma unroll
    for (int o = 16; o; o >>= 1) {
        ss += __shfl_xor_sync(0xffffffffu, ss, o);
        #pragma unroll
        for (int e = 0; e < 16; e++) acc[e] += __shfl_xor_sync(0xffffffffu, acc[e], o);
    }
    if (lane == 0) {
        float rx = rsqrtf(ss + 1e-12f);
        float logits[16], probs[16];
        #pragma unroll
        for (int e = 0; e < 16; e++)
            logits[e] = acc[e] * rx * g_simnorm[16 + e] - sigmoidf_(fgates[e]);
        gating16(logits, probs);
        // block mask: b = row / T, n = (row % T) / W
        float mask = g_bmask[(row >> 12) * 64 + ((row & 4095) >> 6)];
        float* dst = g_rw + row * EE;
        #pragma unroll
        for (int e = 0; e < 16; e++) dst[e] = probs[e] * mask;
    }
}

// ---------------- RoPE on q,k halves of g_qkv ----------------
__global__ void rope_kernel(const int* __restrict__ pos_ids) {
    int idx = blockIdx.x * blockDim.x + threadIdx.x;   // 2 * 16384 * 16 * 32 = 16,777,216
    int i = idx & 31;
    int e = (idx >> 5) & 15;
    int row = (idx >> 9) & 16383;
    int sel = idx >> 23;          // 0 = q, 1 = k
    float* p = g_qkv + (size_t)row * 3072 + sel * 1024 + e * 64;
    float x0 = p[i], x1 = p[i + 32];
    float pos = (float)pos_ids[row];
    float inv = expf(-9.210340371976184f * ((float)i * (1.f / 32.f)));  // 10000^{-i/32}
    float ang = pos * inv;
    float cs = cosf(ang), sn = sinf(ang);
    p[i] = x0 * cs - x1 * sn;
    p[i + 32] = x1 * cs + x0 * sn;
}

// ---------------- block-local causal attention, rw folded into ctx ----------------
// grid = B*E*N*2 (half = 32 query rows per block), 256 threads = 8 warps x 4 rows.
__global__ void __launch_bounds__(256) attn_kernel() {
    int bid = blockIdx.x;
    int half = bid & 1;
    int n = (bid >> 1) & 63;
    int e = (bid >> 7) & 15;
    int b = bid >> 11;

    __shared__ float Qs[32][64];
    __shared__ float Ks[64][65];
    __shared__ float Vs[64][65];
    __shared__ float Ps[8][64];

    int tid = threadIdx.x, lane = tid & 31, w = tid >> 5;
    size_t rowbase = (size_t)(b * TT + n * 64);

    // load K,V (full 64x64 tiles)
    #pragma unroll
    for (int it = 0; it < 4; it++) {
        int t4 = tid + it * 256;          // 0..1023
        int r = t4 >> 4, c4 = (t4 & 15) << 2;
        const float* src = g_qkv + (rowbase + r) * 3072 + e * 64 + c4;
        float4 kv = *(const float4*)(src + 1024);
        float4 vv = *(const float4*)(src + 2048);
        Ks[r][c4 + 0] = kv.x; Ks[r][c4 + 1] = kv.y; Ks[r][c4 + 2] = kv.z; Ks[r][c4 + 3] = kv.w;
        Vs[r][c4 + 0] = vv.x; Vs[r][c4 + 1] = vv.y; Vs[r][c4 + 2] = vv.z; Vs[r][c4 + 3] = vv.w;
    }
    // load Q (32 rows)
    #pragma unroll
    for (int it = 0; it < 2; it++) {
        int t4 = tid + it * 256;          // 0..511
        int r = t4 >> 4, c4 = (t4 & 15) << 2;
        const float4 qv = *(const float4*)(g_qkv + (rowbase + half * 32 + r) * 3072 + e * 64 + c4);
        *(float4*)&Qs[r][c4] = qv;
    }
    __syncthreads();

    for (int rr = 0; rr < 4; rr++) {
        int rl = w * 4 + rr;          // local row 0..31
        int rg = half * 32 + rl;      // global row in window 0..63
        const float* qrow = Qs[rl];
        float s0 = 0.f, s1 = 0.f;
        #pragma unroll
        for (int d = 0; d < 64; d++) {
            float qd = qrow[d];
            s0 += qd * Ks[lane][d];
            s1 += qd * Ks[lane + 32][d];
        }
        s0 *= 0.125f; s1 *= 0.125f;
        if (lane > rg) s0 = NEGV;
        if (lane + 32 > rg) s1 = NEGV;
        float m = fmaxf(s0, s1);
        #pragma unroll
        for (int o = 16; o; o >>= 1) m = fmaxf(m, __shfl_xor_sync(0xffffffffu, m, o));
        float e0 = expf(s0 - m), e1 = expf(s1 - m);
        float sum = e0 + e1;
        #pragma unroll
        for (int o = 16; o; o >>= 1) sum += __shfl_xor_sync(0xffffffffu, sum, o);
        float inv = 1.f / sum;
        Ps[w][lane] = e0 * inv;
        Ps[w][lane + 32] = e1 * inv;
        __syncwarp();
        float c0 = 0.f, c1 = 0.f;
        #pragma unroll
        for (int j = 0; j < 64; j++) {
            float pj = Ps[w][j];
            c0 += pj * Vs[j][lane];
            c1 += pj * Vs[j][lane + 32];
        }
        float rwv = g_rw[(rowbase + rg) * EE + e];
        float* dst = g_wctx + (rowbase + rg) * 1024 + e * 64;
        dst[lane] = c0 * rwv;
        dst[lane + 32] = c1 * rwv;
        __syncwarp();
    }
}

// ---------------- launch ----------------
extern "C" void kernel_launch(void* const* d_in, const int* in_sizes, int n_in,
                              void* d_out, int out_size) {
    const float* hs      = (const float*)d_in[0];
    const int*   pos     = (const int*)d_in[1];
    const float* cw      = (const float*)d_in[2];
    const float* cb      = (const float*)d_in[3];
    const float* gsim    = (const float*)d_in[4];
    const float* ggates  = (const float*)d_in[5];
    const float* thr     = (const float*)d_in[6];
    const float* fsim    = (const float*)d_in[7];
    const float* fgates  = (const float*)d_in[8];
    const float* qp      = (const float*)d_in[9];
    const float* kp      = (const float*)d_in[10];
    const float* vp      = (const float*)d_in[11];
    const float* op      = (const float*)d_in[12];
    float* out = (float*)d_out;

    // prep: weight repacks + sim norms
    repack_qkv_kernel<<<(3072 * 1024) / 256, 256>>>(qp, kp, vp);
    repack_o_kernel<<<(1024 * 1024) / 256, 256>>>(op);
    simnorm_kernel<<<1, 1024>>>(gsim, fsim);

    // compress GEMM: (256 x 65536) @ (65536 x 1024), split-K=16
    {
        float* compP;
        cudaGetSymbolAddress((void**)&compP, g_compP);
        dim3 grid(1024 / 128, 256 / 128, SPLITK);
        sgemm_nt<1><<<grid, 256>>>(hs, cw, compP, MROWS, CC, 65536, 65536, 65536 / SPLITK);
        compress_epilogue_kernel<<<(MROWS * CC) / 256, 256>>>(cb);
    }

    // gating
    g_gate_kernel<<<MROWS, 32>>>(gsim, ggates, thr);
    f_gate_kernel<<<MT / 8, 256>>>(hs, fsim, fgates);

    // QKV GEMM: (16384 x 1024) @ (1024 x 3072)
    {
        float* qkv;
        cudaGetSymbolAddress((void**)&qkv, g_qkv);
        float* wqkv;
        cudaGetSymbolAddress((void**)&wqkv, g_Wqkv);
        dim3 grid(3072 / 128, MT / 128, 1);
        sgemm_nt<0><<<grid, 256>>>(hs, wqkv, qkv, MT, 3072, 1024, 1024, 1024);
    }

    // RoPE on q,k
    rope_kernel<<<(2 * MT * EE * 32) / 256, 256>>>(pos);

    // attention (rw folded in)
    attn_kernel<<<BB * EE * NBLK * 2, 256>>>();

    // output GEMM: (16384 x 1024) @ (1024 x 1024) -> d_out
    {
        float* wctx;
        cudaGetSymbolAddress((void**)&wctx, g_wctx);
        float* ot;
        cudaGetSymbolAddress((void**)&ot, g_Ot);
        dim3 grid(1024 / 128, MT / 128, 1);
        sgemm_nt<0><<<grid, 256>>>(wctx, ot, out, MT, 1024, 1024, 1024, 1024);
    }
}

// round 12
// speedup vs baseline: 2.0058x; 2.0058x over previous
#include <cuda_runtime.h>
#include <cuda_bf16.h>
#include <math.h>
#include <stdint.h>

// Problem constants
#define BB 4
#define TT 4096
#define CC 1024
#define EE 16
#define NBLK 64          // T/W
#define MROWS 256        // B*N
#define MT 16384         // B*T
#define NEGV -1e9f
#define SPLITK 32

// ---------------- scratch (device globals; no allocation) ----------------
__device__ __nv_bfloat16 g_hs_hi[(size_t)MT * CC];
__device__ __nv_bfloat16 g_hs_lo[(size_t)MT * CC];
__device__ __nv_bfloat16 g_cw_hi[(size_t)CC * 65536];
__device__ __nv_bfloat16 g_wq_hi[3072 * 1024];
__device__ __nv_bfloat16 g_wq_lo[3072 * 1024];
__device__ __nv_bfloat16 g_ot_hi[1024 * 1024];
__device__ __nv_bfloat16 g_ot_lo[1024 * 1024];
__device__ __nv_bfloat16 g_wctx_hi[(size_t)MT * 1024];
__device__ __nv_bfloat16 g_wctx_lo[(size_t)MT * 1024];
__device__ float g_simnorm[32];
__device__ float g_compP[(size_t)SPLITK * MROWS * CC];
__device__ float g_comp[MROWS * CC];
__device__ float g_bmask[MROWS];
__device__ float g_rw[MT * EE];
__device__ float g_qkv[(size_t)MT * 3072];

// ---------------- PTX helpers (base sm_103-safe: mma.sync / ldmatrix / cp.async) --------
__device__ __forceinline__ uint32_t smem_u32(const void* p) {
    uint32_t a;
    asm("{ .reg .u64 t; cvta.to.shared.u64 t, %1; cvt.u32.u64 %0, t; }" : "=r"(a) : "l"(p));
    return a;
}
__device__ __forceinline__ void cpa16(uint32_t s, const void* g) {
    asm volatile("cp.async.cg.shared.global [%0], [%1], 16;" :: "r"(s), "l"(g));
}
#define CPA_COMMIT() asm volatile("cp.async.commit_group;" ::: "memory")
#define CPA_WAIT1()  asm volatile("cp.async.wait_group 1;" ::: "memory")
#define CPA_WAIT0()  asm volatile("cp.async.wait_group 0;" ::: "memory")
#define LDSM4(r, a) asm volatile( \
    "ldmatrix.sync.aligned.m8n8.x4.shared.b16 {%0,%1,%2,%3}, [%4];" \
    : "=r"((r)[0]), "=r"((r)[1]), "=r"((r)[2]), "=r"((r)[3]) : "r"(a))
#define MMA16816(c, a, b0, b1) asm volatile( \
    "mma.sync.aligned.m16n8k16.row.col.f32.bf16.bf16.f32 " \
    "{%0,%1,%2,%3},{%4,%5,%6,%7},{%8,%9},{%0,%1,%2,%3};" \
    : "+f"((c)[0]), "+f"((c)[1]), "+f"((c)[2]), "+f"((c)[3]) \
    : "r"((a)[0]), "r"((a)[1]), "r"((a)[2]), "r"((a)[3]), "r"(b0), "r"(b1))

// ---------------- bf16 split helper ----------------
__device__ __forceinline__ void split2(float v, __nv_bfloat16& h, __nv_bfloat16& l) {
    h = __float2bfloat16(v);
    l = __float2bfloat16(v - __bfloat162float(h));
}

// ---------------- conversion kernels ----------------
__global__ void conv_hs_kernel(const float* __restrict__ s) {
    size_t i = (size_t)blockIdx.x * blockDim.x + threadIdx.x;  // over MT*CC/4
    float4 v = ((const float4*)s)[i];
    __nv_bfloat16 h0, h1, h2, h3, l0, l1, l2, l3;
    split2(v.x, h0, l0); split2(v.y, h1, l1); split2(v.z, h2, l2); split2(v.w, h3, l3);
    ((__nv_bfloat162*)g_hs_hi)[2 * i]     = __nv_bfloat162(h0, h1);
    ((__nv_bfloat162*)g_hs_hi)[2 * i + 1] = __nv_bfloat162(h2, h3);
    ((__nv_bfloat162*)g_hs_lo)[2 * i]     = __nv_bfloat162(l0, l1);
    ((__nv_bfloat162*)g_hs_lo)[2 * i + 1] = __nv_bfloat162(l2, l3);
}
__global__ void conv_cw_hi_kernel(const float* __restrict__ s) {
    size_t i = (size_t)blockIdx.x * blockDim.x + threadIdx.x;  // over CC*65536/4
    float4 v = ((const float4*)s)[i];
    ((__nv_bfloat162*)g_cw_hi)[2 * i] =
        __nv_bfloat162(__float2bfloat16(v.x), __float2bfloat16(v.y));
    ((__nv_bfloat162*)g_cw_hi)[2 * i + 1] =
        __nv_bfloat162(__float2bfloat16(v.z), __float2bfloat16(v.w));
}
__global__ void repack_qkv_bf16(const float* __restrict__ qp, const float* __restrict__ kp,
                                const float* __restrict__ vp) {
    int idx = blockIdx.x * blockDim.x + threadIdx.x;   // over 3072*1024
    if (idx >= 3072 * 1024) return;
    int j = idx >> 10, c = idx & 1023;
    int sel = j >> 10;
    int jj = j & 1023;
    int e = jj >> 6, d = jj & 63;
    const float* src = (sel == 0) ? qp : (sel == 1) ? kp : vp;
    float v = src[(e << 16) + (c << 6) + d];
    __nv_bfloat16 h, l; split2(v, h, l);
    g_wq_hi[idx] = h; g_wq_lo[idx] = l;
}
__global__ void repack_o_bf16(const float* __restrict__ op) {
    int idx = blockIdx.x * blockDim.x + threadIdx.x;   // over 1024*1024
    if (idx >= 1024 * 1024) return;
    int c = idx >> 10, kk = idx & 1023;
    float v = op[kk * 1024 + c];
    __nv_bfloat16 h, l; split2(v, h, l);
    g_ot_hi[idx] = h; g_ot_lo[idx] = l;
}

__global__ void simnorm_kernel(const float* __restrict__ gsim, const float* __restrict__ fsim) {
    int w = threadIdx.x >> 5;   // 0..31
    int lane = threadIdx.x & 31;
    int e = w & 15;
    const float* s = (w < 16) ? gsim : fsim;
    float acc = 0.f;
    for (int c = lane; c < CC; c += 32) {
        float v = s[c * EE + e];
        acc += v * v;
    }
    #pragma unroll
    for (int o = 16; o; o >>= 1) acc += __shfl_xor_sync(0xffffffffu, acc, o);
    if (lane == 0) g_simnorm[w] = rsqrtf(acc + 1e-12f);
}

// ---------------- mma.sync split-bf16 NT GEMM ----------------
// C[M,N] = sum of split terms of A[M,K] * B[N,K]^T, fp32 accum.
// NS==3: Ah*Bh + Ah*Bl + Al*Bh.  NS==1: Ah*Bh only.
// CTA 128x128, 8 warps (4x2 -> 32x64 warp tiles), K-chunk 32.
// cp.async double-buffered smem, row stride 40 bf16 (80B, conflict-free LDSM).
// EPI 0: C[r*N+c] = acc.  EPI 1: C += blockIdx.z*M*N (split-K partial buffers).
#define GT_TILE 10240                 // 128 rows * 80B
template <int EPI, int NS>
__global__ void __launch_bounds__(256, 1)
gemm_mma(const __nv_bfloat16* __restrict__ Ah, const __nv_bfloat16* __restrict__ Al,
         const __nv_bfloat16* __restrict__ Bh, const __nv_bfloat16* __restrict__ Bl,
         float* __restrict__ C, int M, int N, int lda_, int ldb_, int kLen) {
    extern __shared__ char sm[];
    const int NTILE = (NS == 3) ? 4 : 2;
    const int STAGE = NTILE * GT_TILE;
    const int tid = threadIdx.x;
    const int wid = tid >> 5, lane = tid & 31;
    const int mw = wid >> 1, nw = wid & 1;
    const size_t lda = (size_t)lda_, ldb = (size_t)ldb_;
    const size_t kBase = (size_t)blockIdx.z * kLen;

    const __nv_bfloat16* srcs[4];
    size_t lds[4];
    srcs[0] = Ah + (size_t)blockIdx.y * 128 * lda + kBase;  lds[0] = lda;
    if (NS == 3) {
        srcs[1] = Al + (size_t)blockIdx.y * 128 * lda + kBase;  lds[1] = lda;
        srcs[2] = Bh + (size_t)blockIdx.x * 128 * ldb + kBase;  lds[2] = ldb;
        srcs[3] = Bl + (size_t)blockIdx.x * 128 * ldb + kBase;  lds[3] = ldb;
    } else {
        srcs[1] = Bh + (size_t)blockIdx.x * 128 * ldb + kBase;  lds[1] = ldb;
    }
    const int offB = (NS == 3) ? 2 * GT_TILE : GT_TILE;   // Bh tile offset in stage
    const uint32_t smb = smem_u32(sm);

    float acc[2][8][4];
    #pragma unroll
    for (int i = 0; i < 2; i++)
        #pragma unroll
        for (int j = 0; j < 8; j++)
            #pragma unroll
            for (int q = 0; q < 4; q++) acc[i][j][q] = 0.f;

    // cp.async issue of one stage
    auto issue = [&](int kc, int buf) {
        uint32_t sbase = smb + buf * STAGE;
        int k0 = kc * 32;
        #pragma unroll
        for (int t = 0; t < NTILE; t++) {
            const __nv_bfloat16* g = srcs[t];
            size_t ld = lds[t];
            #pragma unroll
            for (int i = 0; i < 2; i++) {
                int id = tid + i * 256;          // 0..511 (128 rows x 4 chunks)
                int row = id >> 2, ch = id & 3;
                cpa16(sbase + t * GT_TILE + row * 80 + ch * 16,
                      g + (size_t)row * ld + k0 + ch * 8);
            }
        }
        CPA_COMMIT();
    };

    issue(0, 0);
    const int nc = kLen >> 5;
    for (int c = 0; c < nc; c++) {
        int buf = c & 1;
        if (c + 1 < nc) { issue(c + 1, buf ^ 1); CPA_WAIT1(); }
        else            { CPA_WAIT0(); }
        __syncthreads();

        uint32_t sb = smb + buf * STAGE;
        #pragma unroll
        for (int ks = 0; ks < 2; ks++) {
            uint32_t a_h[2][4], a_l[2][4];
            #pragma unroll
            for (int mi = 0; mi < 2; mi++) {
                int row = mw * 32 + mi * 16 + (lane & 15);
                uint32_t ad = sb + row * 80 + (ks * 2 + (lane >> 4)) * 16;
                LDSM4(a_h[mi], ad);
                if (NS == 3) LDSM4(a_l[mi], ad + GT_TILE);
            }
            uint32_t b_h[8][2], b_l[8][2];
            #pragma unroll
            for (int j = 0; j < 4; j++) {
                int row = nw * 64 + j * 16 + ((lane >> 4) & 1) * 8 + (lane & 7);
                uint32_t ad = sb + offB + row * 80 + (ks * 2 + ((lane >> 3) & 1)) * 16;
                uint32_t r[4];
                LDSM4(r, ad);
                b_h[2 * j][0] = r[0]; b_h[2 * j][1] = r[1];
                b_h[2 * j + 1][0] = r[2]; b_h[2 * j + 1][1] = r[3];
                if (NS == 3) {
                    LDSM4(r, ad + GT_TILE);
                    b_l[2 * j][0] = r[0]; b_l[2 * j][1] = r[1];
                    b_l[2 * j + 1][0] = r[2]; b_l[2 * j + 1][1] = r[3];
                }
            }
            #pragma unroll
            for (int mi = 0; mi < 2; mi++)
                #pragma unroll
                for (int nj = 0; nj < 8; nj++) {
                    MMA16816(acc[mi][nj], a_h[mi], b_h[nj][0], b_h[nj][1]);
                    if (NS == 3) {
                        MMA16816(acc[mi][nj], a_h[mi], b_l[nj][0], b_l[nj][1]);
                        MMA16816(acc[mi][nj], a_l[mi], b_h[nj][0], b_h[nj][1]);
                    }
                }
        }
        __syncthreads();
    }

    float* Cb = C + (EPI ? (size_t)blockIdx.z * M * N : (size_t)0);
    #pragma unroll
    for (int mi = 0; mi < 2; mi++)
        #pragma unroll
        for (int nj = 0; nj < 8; nj++) {
            int r0 = blockIdx.y * 128 + mw * 32 + mi * 16 + (lane >> 2);
            int c0 = blockIdx.x * 128 + nw * 64 + nj * 8 + (lane & 3) * 2;
            float2 v0 = make_float2(acc[mi][nj][0], acc[mi][nj][1]);
            float2 v1 = make_float2(acc[mi][nj][2], acc[mi][nj][3]);
            *(float2*)&Cb[(size_t)r0 * N + c0] = v0;
            *(float2*)&Cb[(size_t)(r0 + 8) * N + c0] = v1;
        }
}

// ---------------- compress epilogue: sum split-K partials + bias + relu ----------------
__global__ void compress_epilogue_kernel(const float* __restrict__ cb) {
    int i = blockIdx.x * blockDim.x + threadIdx.x;  // over 256*1024
    if (i >= MROWS * CC) return;
    float s = cb[i & 1023];
    #pragma unroll
    for (int z = 0; z < SPLITK; z++) s += g_compP[(size_t)z * (MROWS * CC) + i];
    g_comp[i] = fmaxf(s, 0.f);
}

// ---------------- gating (exact replica of reference semantics, E=16) ----------------
__device__ __forceinline__ void gating16(const float* logits, float* probs) {
    float gated[16];
    bool act[16];
    int nact = 0;
    #pragma unroll
    for (int e = 0; e < 16; e++) {
        gated[e] = fmaxf(logits[e], 0.f);
        act[e] = gated[e] > 0.f;
        nact += act[e] ? 1 : 0;
    }
    if (nact == 0) {
        int i1 = 0; float b1 = logits[0];
        #pragma unroll
        for (int e = 1; e < 16; e++) if (logits[e] > b1) { b1 = logits[e]; i1 = e; }
        int i2 = -1; float b2 = -3.4e38f;
        #pragma unroll
        for (int e = 0; e < 16; e++) if (e != i1 && logits[e] > b2) { b2 = logits[e]; i2 = e; }
        #pragma unroll
        for (int e = 0; e < 16; e++) act[e] = (e == i1) || (e == i2);
    }
    float m = -3.4e38f;
    float msk[16];
    #pragma unroll
    for (int e = 0; e < 16; e++) {
        msk[e] = act[e] ? gated[e] : NEGV;
        m = fmaxf(m, msk[e]);
    }
    float s = 0.f;
    #pragma unroll
    for (int e = 0; e < 16; e++) { float x = expf(msk[e] - m); probs[e] = x; s += x; }
    float inv = 1.f / s;
    #pragma unroll
    for (int e = 0; e < 16; e++) probs[e] *= inv;
}

__device__ __forceinline__ float sigmoidf_(float x) { return 1.f / (1.f + expf(-x)); }

__global__ void g_gate_kernel(const float* __restrict__ gsim, const float* __restrict__ ggates,
                              const float* __restrict__ thr) {
    int row = blockIdx.x;
    int lane = threadIdx.x;
    const float* x = g_comp + row * CC;
    float ss = 0.f;
    float acc[16];
    #pragma unroll
    for (int e = 0; e < 16; e++) acc[e] = 0.f;
    for (int c = lane; c < CC; c += 32) {
        float xv = x[c];
        ss += xv * xv;
        const float* sr = gsim + c * EE;
        #pragma unroll
        for (int e = 0; e < 16; e++) acc[e] += xv * sr[e];
    }
    #pragma unroll
    for (int o = 16; o; o >>= 1) {
        ss += __shfl_xor_sync(0xffffffffu, ss, o);
        #pragma unroll
        for (int e = 0; e < 16; e++) acc[e] += __shfl_xor_sync(0xffffffffu, acc[e], o);
    }
    if (lane == 0) {
        float rx = rsqrtf(ss + 1e-12f);
        float logits[16], probs[16];
        #pragma unroll
        for (int e = 0; e < 16; e++)
            logits[e] = acc[e] * rx * g_simnorm[e] - sigmoidf_(ggates[e]);
        gating16(logits, probs);
        float imp = 0.f;
        #pragma unroll
        for (int e = 0; e < 16; e++) imp = fmaxf(imp, probs[e]);
        g_bmask[row] = (imp - thr[0] > 0.f) ? 1.f : 0.f;
    }
}

__global__ void f_gate_kernel(const float* __restrict__ hs, const float* __restrict__ fsim,
                              const float* __restrict__ fgates) {
    int row = blockIdx.x * 8 + (threadIdx.x >> 5);
    int lane = threadIdx.x & 31;
    const float* x = hs + (size_t)row * CC;
    float ss = 0.f;
    float acc[16];
    #pragma unroll
    for (int e = 0; e < 16; e++) acc[e] = 0.f;
    for (int c = lane; c < CC; c += 32) {
        float xv = x[c];
        ss += xv * xv;
        const float* sr = fsim + c * EE;
        #pragma unroll
        for (int e = 0; e < 16; e++) acc[e] += xv * sr[e];
    }
    #pragma unroll
    for (int o = 16; o; o >>= 1) {
        ss += __shfl_xor_sync(0xffffffffu, ss, o);
        #pragma unroll
        for (int e = 0; e < 16; e++) acc[e] += __shfl_xor_sync(0xffffffffu, acc[e], o);
    }
    if (lane == 0) {
        float rx = rsqrtf(ss + 1e-12f);
        float logits[16], probs[16];
        #pragma unroll
        for (int e = 0; e < 16; e++)
            logits[e] = acc[e] * rx * g_simnorm[16 + e] - sigmoidf_(fgates[e]);
        gating16(logits, probs);
        float mask = g_bmask[(row >> 12) * 64 + ((row & 4095) >> 6)];
        float* dst = g_rw + row * EE;
        #pragma unroll
        for (int e = 0; e < 16; e++) dst[e] = probs[e] * mask;
    }
}

// ---------------- RoPE on q,k halves of g_qkv ----------------
__global__ void rope_kernel(const int* __restrict__ pos_ids) {
    int idx = blockIdx.x * blockDim.x + threadIdx.x;   // 2 * 16384 * 16 * 32
    int i = idx & 31;
    int e = (idx >> 5) & 15;
    int row = (idx >> 9) & 16383;
    int sel = idx >> 23;          // 0 = q, 1 = k
    float* p = g_qkv + (size_t)row * 3072 + sel * 1024 + e * 64;
    float x0 = p[i], x1 = p[i + 32];
    float pos = (float)pos_ids[row];
    float inv = expf(-9.210340371976184f * ((float)i * (1.f / 32.f)));  // 10000^{-i/32}
    float ang = pos * inv;
    float cs = cosf(ang), sn = sinf(ang);
    p[i] = x0 * cs - x1 * sn;
    p[i + 32] = x1 * cs + x0 * sn;
}

// ---------------- block-local causal attention, rw folded; writes wctx hi/lo bf16 ----------------
__global__ void __launch_bounds__(256) attn_kernel() {
    int bid = blockIdx.x;
    int half = bid & 1;
    int n = (bid >> 1) & 63;
    int e = (bid >> 7) & 15;
    int b = bid >> 11;

    __shared__ float Qs[32][64];
    __shared__ float Ks[64][65];
    __shared__ float Vs[64][65];
    __shared__ float Ps[8][64];

    int tid = threadIdx.x, lane = tid & 31, w = tid >> 5;
    size_t rowbase = (size_t)(b * TT + n * 64);

    #pragma unroll
    for (int it = 0; it < 4; it++) {
        int t4 = tid + it * 256;
        int r = t4 >> 4, c4 = (t4 & 15) << 2;
        const float* src = g_qkv + (rowbase + r) * 3072 + e * 64 + c4;
        float4 kv = *(const float4*)(src + 1024);
        float4 vv = *(const float4*)(src + 2048);
        Ks[r][c4 + 0] = kv.x; Ks[r][c4 + 1] = kv.y; Ks[r][c4 + 2] = kv.z; Ks[r][c4 + 3] = kv.w;
        Vs[r][c4 + 0] = vv.x; Vs[r][c4 + 1] = vv.y; Vs[r][c4 + 2] = vv.z; Vs[r][c4 + 3] = vv.w;
    }
    #pragma unroll
    for (int it = 0; it < 2; it++) {
        int t4 = tid + it * 256;
        int r = t4 >> 4, c4 = (t4 & 15) << 2;
        const float4 qv = *(const float4*)(g_qkv + (rowbase + half * 32 + r) * 3072 + e * 64 + c4);
        *(float4*)&Qs[r][c4] = qv;
    }
    __syncthreads();

    for (int rr = 0; rr < 4; rr++) {
        int rl = w * 4 + rr;
        int rg = half * 32 + rl;
        const float* qrow = Qs[rl];
        float s0 = 0.f, s1 = 0.f;
        #pragma unroll
        for (int d = 0; d < 64; d++) {
            float qd = qrow[d];
            s0 += qd * Ks[lane][d];
            s1 += qd * Ks[lane + 32][d];
        }
        s0 *= 0.125f; s1 *= 0.125f;
        if (lane > rg) s0 = NEGV;
        if (lane + 32 > rg) s1 = NEGV;
        float m = fmaxf(s0, s1);
        #pragma unroll
        for (int o = 16; o; o >>= 1) m = fmaxf(m, __shfl_xor_sync(0xffffffffu, m, o));
        float e0 = expf(s0 - m), e1 = expf(s1 - m);
        float sum = e0 + e1;
        #pragma unroll
        for (int o = 16; o; o >>= 1) sum += __shfl_xor_sync(0xffffffffu, sum, o);
        float inv = 1.f / sum;
        Ps[w][lane] = e0 * inv;
        Ps[w][lane + 32] = e1 * inv;
        __syncwarp();
        float c0 = 0.f, c1 = 0.f;
        #pragma unroll
        for (int j = 0; j < 64; j++) {
            float pj = Ps[w][j];
            c0 += pj * Vs[j][lane];
            c1 += pj * Vs[j][lane + 32];
        }
        float rwv = g_rw[(rowbase + rg) * EE + e];
        float v0 = c0 * rwv, v1 = c1 * rwv;
        size_t o0 = (rowbase + rg) * 1024 + e * 64 + lane;
        __nv_bfloat16 h, l;
        split2(v0, h, l); g_wctx_hi[o0] = h;      g_wctx_lo[o0] = l;
        split2(v1, h, l); g_wctx_hi[o0 + 32] = h; g_wctx_lo[o0 + 32] = l;
        __syncwarp();
    }
}

// ---------------- launch ----------------
extern "C" void kernel_launch(void* const* d_in, const int* in_sizes, int n_in,
                              void* d_out, int out_size) {
    const float* hs      = (const float*)d_in[0];
    const int*   pos     = (const int*)d_in[1];
    const float* cw      = (const float*)d_in[2];
    const float* cb      = (const float*)d_in[3];
    const float* gsim    = (const float*)d_in[4];
    const float* ggates  = (const float*)d_in[5];
    const float* thr     = (const float*)d_in[6];
    const float* fsim    = (const float*)d_in[7];
    const float* fgates  = (const float*)d_in[8];
    const float* qp      = (const float*)d_in[9];
    const float* kp      = (const float*)d_in[10];
    const float* vp      = (const float*)d_in[11];
    const float* op      = (const float*)d_in[12];
    float* out = (float*)d_out;

    const int SMEM3 = 2 * 4 * GT_TILE;   // 81920
    const int SMEM1 = 2 * 2 * GT_TILE;   // 40960
    cudaFuncSetAttribute(gemm_mma<0, 3>, cudaFuncAttributeMaxDynamicSharedMemorySize, SMEM3);
    cudaFuncSetAttribute(gemm_mma<1, 1>, cudaFuncAttributeMaxDynamicSharedMemorySize, SMEM1);

    __nv_bfloat16 *hsh, *hsl, *cwh, *wqh, *wql, *oth, *otl, *wch, *wcl;
    float *compP, *qkv;
    cudaGetSymbolAddress((void**)&hsh, g_hs_hi);  cudaGetSymbolAddress((void**)&hsl, g_hs_lo);
    cudaGetSymbolAddress((void**)&cwh, g_cw_hi);
    cudaGetSymbolAddress((void**)&wqh, g_wq_hi);  cudaGetSymbolAddress((void**)&wql, g_wq_lo);
    cudaGetSymbolAddress((void**)&oth, g_ot_hi);  cudaGetSymbolAddress((void**)&otl, g_ot_lo);
    cudaGetSymbolAddress((void**)&wch, g_wctx_hi); cudaGetSymbolAddress((void**)&wcl, g_wctx_lo);
    cudaGetSymbolAddress((void**)&compP, g_compP);
    cudaGetSymbolAddress((void**)&qkv, g_qkv);

    // conversions + repacks + norms
    conv_hs_kernel<<<(MT * CC / 4) / 256, 256>>>(hs);
    conv_cw_hi_kernel<<<(CC * 65536 / 4) / 256, 256>>>(cw);
    repack_qkv_bf16<<<(3072 * 1024) / 256, 256>>>(qp, kp, vp);
    repack_o_bf16<<<(1024 * 1024) / 256, 256>>>(op);
    simnorm_kernel<<<1, 1024>>>(gsim, fsim);

    // compress GEMM (bf16 1-term is exact for the downstream mask when thr < 1/16):
    // (256 x 65536) @ (65536 x 1024), split-K=32
    {
        dim3 grid(1024 / 128, MROWS / 128, SPLITK);
        gemm_mma<1, 1><<<grid, 256, SMEM1>>>(hsh, hsh, cwh, cwh, compP,
                                             MROWS, CC, 65536, 65536, 65536 / SPLITK);
        compress_epilogue_kernel<<<(MROWS * CC) / 256, 256>>>(cb);
    }

    // gating
    g_gate_kernel<<<MROWS, 32>>>(gsim, ggates, thr);
    f_gate_kernel<<<MT / 8, 256>>>(hs, fsim, fgates);

    // QKV GEMM (split-bf16 3-term): (16384 x 1024) @ (1024 x 3072)
    {
        dim3 grid(3072 / 128, MT / 128, 1);
        gemm_mma<0, 3><<<grid, 256, SMEM3>>>(hsh, hsl, wqh, wql, qkv,
                                             MT, 3072, 1024, 1024, 1024);
    }

    // RoPE on q,k
    rope_kernel<<<(2 * MT * EE * 32) / 256, 256>>>(pos);

    // attention (rw folded in, writes wctx hi/lo)
    attn_kernel<<<BB * EE * NBLK * 2, 256>>>();

    // output GEMM (split-bf16 3-term): (16384 x 1024) @ (1024 x 1024) -> d_out
    {
        dim3 grid(1024 / 128, MT / 128, 1);
        gemm_mma<0, 3><<<grid, 256, SMEM3>>>(wch, wcl, oth, otl, out,
                                             MT, 1024, 1024, 1024, 1024);
    }
}

// round 17
// speedup vs baseline: 2.2393x; 1.1165x over previous
#include <cuda_runtime.h>
#include <cuda_bf16.h>
#include <math.h>
#include <stdint.h>

// Problem constants
#define BB 4
#define TT 4096
#define CC 1024
#define EE 16
#define NBLK 64          // T/W
#define MROWS 256        // B*N
#define MT 16384         // B*T
#define NEGV -1e9f
#define SPLITK 32
#define THR_SKIP 0.0625f // max softmax prob over 16 entries >= 1/16: mask==1 if thr < this

// ---------------- scratch (device globals; no allocation) ----------------
__device__ __nv_bfloat16 g_hs_hi[(size_t)MT * CC];
__device__ __nv_bfloat16 g_hs_lo[(size_t)MT * CC];
__device__ __nv_bfloat16 g_cw_hi[(size_t)CC * 65536];
__device__ __nv_bfloat16 g_wq_hi[3072 * 1024];
__device__ __nv_bfloat16 g_wq_lo[3072 * 1024];
__device__ __nv_bfloat16 g_ot_hi[1024 * 1024];
__device__ __nv_bfloat16 g_ot_lo[1024 * 1024];
__device__ __nv_bfloat16 g_wctx_hi[(size_t)MT * 1024];
__device__ __nv_bfloat16 g_wctx_lo[(size_t)MT * 1024];
__device__ float g_simnorm[32];
__device__ float g_compP[(size_t)SPLITK * MROWS * CC];
__device__ float g_comp[MROWS * CC];
__device__ float g_bmask[MROWS];
__device__ float g_rw[MT * EE];
__device__ float g_qkv[(size_t)MT * 3072];

// ---------------- PTX helpers (base sm_103-safe: mma.sync / ldmatrix / cp.async) --------
__device__ __forceinline__ uint32_t smem_u32(const void* p) {
    uint32_t a;
    asm("{ .reg .u64 t; cvta.to.shared.u64 t, %1; cvt.u32.u64 %0, t; }" : "=r"(a) : "l"(p));
    return a;
}
__device__ __forceinline__ void cpa16(uint32_t s, const void* g) {
    asm volatile("cp.async.cg.shared.global [%0], [%1], 16;" :: "r"(s), "l"(g));
}
#define CPA_COMMIT() asm volatile("cp.async.commit_group;" ::: "memory")
#define CPA_WAIT1()  asm volatile("cp.async.wait_group 1;" ::: "memory")
#define CPA_WAIT0()  asm volatile("cp.async.wait_group 0;" ::: "memory")
#define LDSM4(r, a) asm volatile( \
    "ldmatrix.sync.aligned.m8n8.x4.shared.b16 {%0,%1,%2,%3}, [%4];" \
    : "=r"((r)[0]), "=r"((r)[1]), "=r"((r)[2]), "=r"((r)[3]) : "r"(a))
#define MMA16816(c, a, b0, b1) asm volatile( \
    "mma.sync.aligned.m16n8k16.row.col.f32.bf16.bf16.f32 " \
    "{%0,%1,%2,%3},{%4,%5,%6,%7},{%8,%9},{%0,%1,%2,%3};" \
    : "+f"((c)[0]), "+f"((c)[1]), "+f"((c)[2]), "+f"((c)[3]) \
    : "r"((a)[0]), "r"((a)[1]), "r"((a)[2]), "r"((a)[3]), "r"(b0), "r"(b1))

// ---------------- bf16 split helper ----------------
__device__ __forceinline__ void split2(float v, __nv_bfloat16& h, __nv_bfloat16& l) {
    h = __float2bfloat16(v);
    l = __float2bfloat16(v - __bfloat162float(h));
}

// ---------------- conversion kernels ----------------
__global__ void conv_hs_kernel(const float* __restrict__ s) {
    size_t i = (size_t)blockIdx.x * blockDim.x + threadIdx.x;  // over MT*CC/4
    float4 v = ((const float4*)s)[i];
    __nv_bfloat16 h0, h1, h2, h3, l0, l1, l2, l3;
    split2(v.x, h0, l0); split2(v.y, h1, l1); split2(v.z, h2, l2); split2(v.w, h3, l3);
    ((__nv_bfloat162*)g_hs_hi)[2 * i]     = __nv_bfloat162(h0, h1);
    ((__nv_bfloat162*)g_hs_hi)[2 * i + 1] = __nv_bfloat162(h2, h3);
    ((__nv_bfloat162*)g_hs_lo)[2 * i]     = __nv_bfloat162(l0, l1);
    ((__nv_bfloat162*)g_hs_lo)[2 * i + 1] = __nv_bfloat162(l2, l3);
}
// gated: only needed when thr >= 1/16 (otherwise block mask is identically 1)
__global__ void conv_cw_hi_kernel(const float* __restrict__ s, const float* __restrict__ thr) {
    if (thr[0] < THR_SKIP) return;
    size_t i = (size_t)blockIdx.x * blockDim.x + threadIdx.x;  // over CC*65536/4
    float4 v = ((const float4*)s)[i];
    ((__nv_bfloat162*)g_cw_hi)[2 * i] =
        __nv_bfloat162(__float2bfloat16(v.x), __float2bfloat16(v.y));
    ((__nv_bfloat162*)g_cw_hi)[2 * i + 1] =
        __nv_bfloat162(__float2bfloat16(v.z), __float2bfloat16(v.w));
}
__global__ void repack_qkv_bf16(const float* __restrict__ qp, const float* __restrict__ kp,
                                const float* __restrict__ vp) {
    int idx = blockIdx.x * blockDim.x + threadIdx.x;   // over 3072*1024
    if (idx >= 3072 * 1024) return;
    int j = idx >> 10, c = idx & 1023;
    int sel = j >> 10;
    int jj = j & 1023;
    int e = jj >> 6, d = jj & 63;
    const float* src = (sel == 0) ? qp : (sel == 1) ? kp : vp;
    float v = src[(e << 16) + (c << 6) + d];
    __nv_bfloat16 h, l; split2(v, h, l);
    g_wq_hi[idx] = h; g_wq_lo[idx] = l;
}
__global__ void repack_o_bf16(const float* __restrict__ op) {
    int idx = blockIdx.x * blockDim.x + threadIdx.x;   // over 1024*1024
    if (idx >= 1024 * 1024) return;
    int c = idx >> 10, kk = idx & 1023;
    float v = op[kk * 1024 + c];
    __nv_bfloat16 h, l; split2(v, h, l);
    g_ot_hi[idx] = h; g_ot_lo[idx] = l;
}

__global__ void simnorm_kernel(const float* __restrict__ gsim, const float* __restrict__ fsim) {
    int w = threadIdx.x >> 5;   // 0..31
    int lane = threadIdx.x & 31;
    int e = w & 15;
    const float* s = (w < 16) ? gsim : fsim;
    float acc = 0.f;
    for (int c = lane; c < CC; c += 32) {
        float v = s[c * EE + e];
        acc += v * v;
    }
    #pragma unroll
    for (int o = 16; o; o >>= 1) acc += __shfl_xor_sync(0xffffffffu, acc, o);
    if (lane == 0) g_simnorm[w] = rsqrtf(acc + 1e-12f);
}

// ---------------- mma.sync split-bf16 NT GEMM ----------------
// C[M,N] = sum of split terms of A[M,K] * B[N,K]^T, fp32 accum.
// NS==3: Ah*Bh + Ah*Bl + Al*Bh.  NS==1: Ah*Bh only.
// CTA 128x128, 8 warps (4x2 -> 32x64 warp tiles), K-chunk 32.
// 3-stage cp.async pipeline, ONE __syncthreads per chunk.
// Row stride 40 bf16 (80B, conflict-free LDSM).
// skip_lt: if non-null and *skip_lt < THR_SKIP, whole kernel is a no-op (gated compress).
// EPI 0: C[r*N+c] = acc.  EPI 1: C += blockIdx.z*M*N (split-K partial buffers).
#define GT_TILE 10240                 // 128 rows * 80B
template <int EPI, int NS>
__global__ void __launch_bounds__(256, 1)
gemm_mma(const __nv_bfloat16* __restrict__ Ah, const __nv_bfloat16* __restrict__ Al,
         const __nv_bfloat16* __restrict__ Bh, const __nv_bfloat16* __restrict__ Bl,
         float* __restrict__ C, int M, int N, int lda_, int ldb_, int kLen,
         const float* __restrict__ skip_lt) {
    if (skip_lt != nullptr && skip_lt[0] < THR_SKIP) return;
    extern __shared__ char sm[];
    const int NTILE = (NS == 3) ? 4 : 2;
    const int STAGE = NTILE * GT_TILE;
    const int tid = threadIdx.x;
    const int wid = tid >> 5, lane = tid & 31;
    const int mw = wid >> 1, nw = wid & 1;
    const size_t lda = (size_t)lda_, ldb = (size_t)ldb_;
    const size_t kBase = (size_t)blockIdx.z * kLen;

    const __nv_bfloat16* srcs[4];
    size_t lds[4];
    srcs[0] = Ah + (size_t)blockIdx.y * 128 * lda + kBase;  lds[0] = lda;
    if (NS == 3) {
        srcs[1] = Al + (size_t)blockIdx.y * 128 * lda + kBase;  lds[1] = lda;
        srcs[2] = Bh + (size_t)blockIdx.x * 128 * ldb + kBase;  lds[2] = ldb;
        srcs[3] = Bl + (size_t)blockIdx.x * 128 * ldb + kBase;  lds[3] = ldb;
    } else {
        srcs[1] = Bh + (size_t)blockIdx.x * 128 * ldb + kBase;  lds[1] = ldb;
    }
    const int offB = (NS == 3) ? 2 * GT_TILE : GT_TILE;   // Bh tile offset in stage
    const uint32_t smb = smem_u32(sm);

    float acc[2][8][4];
    #pragma unroll
    for (int i = 0; i < 2; i++)
        #pragma unroll
        for (int j = 0; j < 8; j++)
            #pragma unroll
            for (int q = 0; q < 4; q++) acc[i][j][q] = 0.f;

    // cp.async issue of one stage
    auto issue = [&](int kc, int buf) {
        uint32_t sbase = smb + buf * STAGE;
        int k0 = kc * 32;
        #pragma unroll
        for (int t = 0; t < NTILE; t++) {
            const __nv_bfloat16* g = srcs[t];
            size_t ld = lds[t];
            #pragma unroll
            for (int i = 0; i < 2; i++) {
                int id = tid + i * 256;          // 0..511 (128 rows x 4 chunks)
                int row = id >> 2, ch = id & 3;
                cpa16(sbase + t * GT_TILE + row * 80 + ch * 16,
                      g + (size_t)row * ld + k0 + ch * 8);
            }
        }
        CPA_COMMIT();
    };

    const int nc = kLen >> 5;   // >= 32 for all our shapes
    issue(0, 0);
    issue(1, 1);
    int buf = 0;
    for (int c = 0; c < nc; c++) {
        // chunk c's group complete when at most 1 newer group pending
        if (c + 1 < nc) CPA_WAIT1();
        else            CPA_WAIT0();
        __syncthreads();   // also orders prev iteration's reads before this iteration's issue
        if (c + 2 < nc) {
            int nb = buf + 2; if (nb >= 3) nb -= 3;
            issue(c + 2, nb);
        }

        uint32_t sb = smb + buf * STAGE;
        #pragma unroll
        for (int ks = 0; ks < 2; ks++) {
            uint32_t a_h[2][4], a_l[2][4];
            #pragma unroll
            for (int mi = 0; mi < 2; mi++) {
                int row = mw * 32 + mi * 16 + (lane & 15);
                uint32_t ad = sb + row * 80 + (ks * 2 + (lane >> 4)) * 16;
                LDSM4(a_h[mi], ad);
                if (NS == 3) LDSM4(a_l[mi], ad + GT_TILE);
            }
            uint32_t b_h[8][2], b_l[8][2];
            #pragma unroll
            for (int j = 0; j < 4; j++) {
                int row = nw * 64 + j * 16 + ((lane >> 4) & 1) * 8 + (lane & 7);
                uint32_t ad = sb + offB + row * 80 + (ks * 2 + ((lane >> 3) & 1)) * 16;
                uint32_t r[4];
                LDSM4(r, ad);
                b_h[2 * j][0] = r[0]; b_h[2 * j][1] = r[1];
                b_h[2 * j + 1][0] = r[2]; b_h[2 * j + 1][1] = r[3];
                if (NS == 3) {
                    LDSM4(r, ad + GT_TILE);
                    b_l[2 * j][0] = r[0]; b_l[2 * j][1] = r[1];
                    b_l[2 * j + 1][0] = r[2]; b_l[2 * j + 1][1] = r[3];
                }
            }
            #pragma unroll
            for (int mi = 0; mi < 2; mi++)
                #pragma unroll
                for (int nj = 0; nj < 8; nj++) {
                    MMA16816(acc[mi][nj], a_h[mi], b_h[nj][0], b_h[nj][1]);
                    if (NS == 3) {
                        MMA16816(acc[mi][nj], a_h[mi], b_l[nj][0], b_l[nj][1]);
                        MMA16816(acc[mi][nj], a_l[mi], b_h[nj][0], b_h[nj][1]);
                    }
                }
        }
        buf++; if (buf >= 3) buf = 0;
    }

    float* Cb = C + (EPI ? (size_t)blockIdx.z * M * N : (size_t)0);
    #pragma unroll
    for (int mi = 0; mi < 2; mi++)
        #pragma unroll
        for (int nj = 0; nj < 8; nj++) {
            int r0 = blockIdx.y * 128 + mw * 32 + mi * 16 + (lane >> 2);
            int c0 = blockIdx.x * 128 + nw * 64 + nj * 8 + (lane & 3) * 2;
            float2 v0 = make_float2(acc[mi][nj][0], acc[mi][nj][1]);
            float2 v1 = make_float2(acc[mi][nj][2], acc[mi][nj][3]);
            *(float2*)&Cb[(size_t)r0 * N + c0] = v0;
            *(float2*)&Cb[(size_t)(r0 + 8) * N + c0] = v1;
        }
}

// ---------------- compress epilogue: sum split-K partials + bias + relu (gated) --------
__global__ void compress_epilogue_kernel(const float* __restrict__ cb,
                                         const float* __restrict__ thr) {
    if (thr[0] < THR_SKIP) return;
    int i = blockIdx.x * blockDim.x + threadIdx.x;  // over 256*1024
    if (i >= MROWS * CC) return;
    float s = cb[i & 1023];
    #pragma unroll
    for (int z = 0; z < SPLITK; z++) s += g_compP[(size_t)z * (MROWS * CC) + i];
    g_comp[i] = fmaxf(s, 0.f);
}

// ---------------- gating (exact replica of reference semantics, E=16) ----------------
__device__ __forceinline__ void gating16(const float* logits, float* probs) {
    float gated[16];
    bool act[16];
    int nact = 0;
    #pragma unroll
    for (int e = 0; e < 16; e++) {
        gated[e] = fmaxf(logits[e], 0.f);
        act[e] = gated[e] > 0.f;
        nact += act[e] ? 1 : 0;
    }
    if (nact == 0) {
        int i1 = 0; float b1 = logits[0];
        #pragma unroll
        for (int e = 1; e < 16; e++) if (logits[e] > b1) { b1 = logits[e]; i1 = e; }
        int i2 = -1; float b2 = -3.4e38f;
        #pragma unroll
        for (int e = 0; e < 16; e++) if (e != i1 && logits[e] > b2) { b2 = logits[e]; i2 = e; }
        #pragma unroll
        for (int e = 0; e < 16; e++) act[e] = (e == i1) || (e == i2);
    }
    float m = -3.4e38f;
    float msk[16];
    #pragma unroll
    for (int e = 0; e < 16; e++) {
        msk[e] = act[e] ? gated[e] : NEGV;
        m = fmaxf(m, msk[e]);
    }
    float s = 0.f;
    #pragma unroll
    for (int e = 0; e < 16; e++) { float x = expf(msk[e] - m); probs[e] = x; s += x; }
    float inv = 1.f / s;
    #pragma unroll
    for (int e = 0; e < 16; e++) probs[e] *= inv;
}

__device__ __forceinline__ float sigmoidf_(float x) { return 1.f / (1.f + expf(-x)); }

__global__ void g_gate_kernel(const float* __restrict__ gsim, const float* __restrict__ ggates,
                              const float* __restrict__ thr) {
    int row = blockIdx.x;
    int lane = threadIdx.x;
    // max softmax prob >= 1/16 always, so mask == 1 whenever thr < 1/16
    if (thr[0] < THR_SKIP) {
        if (lane == 0) g_bmask[row] = 1.f;
        return;
    }
    const float* x = g_comp + row * CC;
    float ss = 0.f;
    float acc[16];
    #pragma unroll
    for (int e = 0; e < 16; e++) acc[e] = 0.f;
    for (int c = lane; c < CC; c += 32) {
        float xv = x[c];
        ss += xv * xv;
        const float* sr = gsim + c * EE;
        #pragma unroll
        for (int e = 0; e < 16; e++) acc[e] += xv * sr[e];
    }
    #pragma unroll
    for (int o = 16; o; o >>= 1) {
        ss += __shfl_xor_sync(0xffffffffu, ss, o);
        #pragma unroll
        for (int e = 0; e < 16; e++) acc[e] += __shfl_xor_sync(0xffffffffu, acc[e], o);
    }
    if (lane == 0) {
        float rx = rsqrtf(ss + 1e-12f);
        float logits[16], probs[16];
        #pragma unroll
        for (int e = 0; e < 16; e++)
            logits[e] = acc[e] * rx * g_simnorm[e] - sigmoidf_(ggates[e]);
        gating16(logits, probs);
        float imp = 0.f;
        #pragma unroll
        for (int e = 0; e < 16; e++) imp = fmaxf(imp, probs[e]);
        g_bmask[row] = (imp - thr[0] > 0.f) ? 1.f : 0.f;
    }
}

__global__ void f_gate_kernel(const float* __restrict__ hs, const float* __restrict__ fsim,
                              const float* __restrict__ fgates) {
    int row = blockIdx.x * 8 + (threadIdx.x >> 5);
    int lane = threadIdx.x & 31;
    const float* x = hs + (size_t)row * CC;
    float ss = 0.f;
    float acc[16];
    #pragma unroll
    for (int e = 0; e < 16; e++) acc[e] = 0.f;
    for (int c = lane; c < CC; c += 32) {
        float xv = x[c];
        ss += xv * xv;
        const float* sr = fsim + c * EE;
        #pragma unroll
        for (int e = 0; e < 16; e++) acc[e] += xv * sr[e];
    }
    #pragma unroll
    for (int o = 16; o; o >>= 1) {
        ss += __shfl_xor_sync(0xffffffffu, ss, o);
        #pragma unroll
        for (int e = 0; e < 16; e++) acc[e] += __shfl_xor_sync(0xffffffffu, acc[e], o);
    }
    if (lane == 0) {
        float rx = rsqrtf(ss + 1e-12f);
        float logits[16], probs[16];
        #pragma unroll
        for (int e = 0; e < 16; e++)
            logits[e] = acc[e] * rx * g_simnorm[16 + e] - sigmoidf_(fgates[e]);
        gating16(logits, probs);
        float mask = g_bmask[(row >> 12) * 64 + ((row & 4095) >> 6)];
        float* dst = g_rw + row * EE;
        #pragma unroll
        for (int e = 0; e < 16; e++) dst[e] = probs[e] * mask;
    }
}

// ---------------- RoPE on q,k halves of g_qkv ----------------
__global__ void rope_kernel(const int* __restrict__ pos_ids) {
    int idx = blockIdx.x * blockDim.x + threadIdx.x;   // 2 * 16384 * 16 * 32
    int i = idx & 31;
    int e = (idx >> 5) & 15;
    int row = (idx >> 9) & 16383;
    int sel = idx >> 23;          // 0 = q, 1 = k
    float* p = g_qkv + (size_t)row * 3072 + sel * 1024 + e * 64;
    float x0 = p[i], x1 = p[i + 32];
    float pos = (float)pos_ids[row];
    float inv = expf(-9.210340371976184f * ((float)i * (1.f / 32.f)));  // 10000^{-i/32}
    float ang = pos * inv;
    float cs = cosf(ang), sn = sinf(ang);
    p[i] = x0 * cs - x1 * sn;
    p[i + 32] = x1 * cs + x0 * sn;
}

// ---------------- block-local causal attention, rw folded; writes wctx hi/lo bf16 ----------------
__global__ void __launch_bounds__(256) attn_kernel() {
    int bid = blockIdx.x;
    int half = bid & 1;
    int n = (bid >> 1) & 63;
    int e = (bid >> 7) & 15;
    int b = bid >> 11;

    __shared__ float Qs[32][64];
    __shared__ float Ks[64][65];
    __shared__ float Vs[64][65];
    __shared__ float Ps[8][64];

    int tid = threadIdx.x, lane = tid & 31, w = tid >> 5;
    size_t rowbase = (size_t)(b * TT + n * 64);

    #pragma unroll
    for (int it = 0; it < 4; it++) {
        int t4 = tid + it * 256;
        int r = t4 >> 4, c4 = (t4 & 15) << 2;
        const float* src = g_qkv + (rowbase + r) * 3072 + e * 64 + c4;
        float4 kv = *(const float4*)(src + 1024);
        float4 vv = *(const float4*)(src + 2048);
        Ks[r][c4 + 0] = kv.x; Ks[r][c4 + 1] = kv.y; Ks[r][c4 + 2] = kv.z; Ks[r][c4 + 3] = kv.w;
        Vs[r][c4 + 0] = vv.x; Vs[r][c4 + 1] = vv.y; Vs[r][c4 + 2] = vv.z; Vs[r][c4 + 3] = vv.w;
    }
    #pragma unroll
    for (int it = 0; it < 2; it++) {
        int t4 = tid + it * 256;
        int r = t4 >> 4, c4 = (t4 & 15) << 2;
        const float4 qv = *(const float4*)(g_qkv + (rowbase + half * 32 + r) * 3072 + e * 64 + c4);
        *(float4*)&Qs[r][c4] = qv;
    }
    __syncthreads();

    for (int rr = 0; rr < 4; rr++) {
        int rl = w * 4 + rr;
        int rg = half * 32 + rl;
        const float* qrow = Qs[rl];
        float s0 = 0.f, s1 = 0.f;
        #pragma unroll
        for (int d = 0; d < 64; d++) {
            float qd = qrow[d];
            s0 += qd * Ks[lane][d];
            s1 += qd * Ks[lane + 32][d];
        }
        s0 *= 0.125f; s1 *= 0.125f;
        if (lane > rg) s0 = NEGV;
        if (lane + 32 > rg) s1 = NEGV;
        float m = fmaxf(s0, s1);
        #pragma unroll
        for (int o = 16; o; o >>= 1) m = fmaxf(m, __shfl_xor_sync(0xffffffffu, m, o));
        float e0 = expf(s0 - m), e1 = expf(s1 - m);
        float sum = e0 + e1;
        #pragma unroll
        for (int o = 16; o; o >>= 1) sum += __shfl_xor_sync(0xffffffffu, sum, o);
        float inv = 1.f / sum;
        Ps[w][lane] = e0 * inv;
        Ps[w][lane + 32] = e1 * inv;
        __syncwarp();
        float c0 = 0.f, c1 = 0.f;
        #pragma unroll
        for (int j = 0; j < 64; j++) {
            float pj = Ps[w][j];
            c0 += pj * Vs[j][lane];
            c1 += pj * Vs[j][lane + 32];
        }
        float rwv = g_rw[(rowbase + rg) * EE + e];
        float v0 = c0 * rwv, v1 = c1 * rwv;
        size_t o0 = (rowbase + rg) * 1024 + e * 64 + lane;
        __nv_bfloat16 h, l;
        split2(v0, h, l); g_wctx_hi[o0] = h;      g_wctx_lo[o0] = l;
        split2(v1, h, l); g_wctx_hi[o0 + 32] = h; g_wctx_lo[o0 + 32] = l;
        __syncwarp();
    }
}

// ---------------- launch ----------------
extern "C" void kernel_launch(void* const* d_in, const int* in_sizes, int n_in,
                              void* d_out, int out_size) {
    const float* hs      = (const float*)d_in[0];
    const int*   pos     = (const int*)d_in[1];
    const float* cw      = (const float*)d_in[2];
    const float* cb      = (const float*)d_in[3];
    const float* gsim    = (const float*)d_in[4];
    const float* ggates  = (const float*)d_in[5];
    const float* thr     = (const float*)d_in[6];
    const float* fsim    = (const float*)d_in[7];
    const float* fgates  = (const float*)d_in[8];
    const float* qp      = (const float*)d_in[9];
    const float* kp      = (const float*)d_in[10];
    const float* vp      = (const float*)d_in[11];
    const float* op      = (const float*)d_in[12];
    float* out = (float*)d_out;

    const int SMEM3 = 3 * 4 * GT_TILE;   // 122880
    const int SMEM1 = 3 * 2 * GT_TILE;   // 61440
    cudaFuncSetAttribute(gemm_mma<0, 3>, cudaFuncAttributeMaxDynamicSharedMemorySize, SMEM3);
    cudaFuncSetAttribute(gemm_mma<1, 1>, cudaFuncAttributeMaxDynamicSharedMemorySize, SMEM1);

    __nv_bfloat16 *hsh, *hsl, *cwh, *wqh, *wql, *oth, *otl, *wch, *wcl;
    float *compP, *qkv;
    cudaGetSymbolAddress((void**)&hsh, g_hs_hi);  cudaGetSymbolAddress((void**)&hsl, g_hs_lo);
    cudaGetSymbolAddress((void**)&cwh, g_cw_hi);
    cudaGetSymbolAddress((void**)&wqh, g_wq_hi);  cudaGetSymbolAddress((void**)&wql, g_wq_lo);
    cudaGetSymbolAddress((void**)&oth, g_ot_hi);  cudaGetSymbolAddress((void**)&otl, g_ot_lo);
    cudaGetSymbolAddress((void**)&wch, g_wctx_hi); cudaGetSymbolAddress((void**)&wcl, g_wctx_lo);
    cudaGetSymbolAddress((void**)&compP, g_compP);
    cudaGetSymbolAddress((void**)&qkv, g_qkv);

    // conversions + repacks + norms
    conv_hs_kernel<<<(MT * CC / 4) / 256, 256>>>(hs);
    conv_cw_hi_kernel<<<(CC * 65536 / 4) / 256, 256>>>(cw, thr);
    repack_qkv_bf16<<<(3072 * 1024) / 256, 256>>>(qp, kp, vp);
    repack_o_bf16<<<(1024 * 1024) / 256, 256>>>(op);
    simnorm_kernel<<<1, 1024>>>(gsim, fsim);

    // compress GEMM (bf16 1-term; whole path no-ops when thr < 1/16 since mask==1):
    // (256 x 65536) @ (65536 x 1024), split-K=32
    {
        dim3 grid(1024 / 128, MROWS / 128, SPLITK);
        gemm_mma<1, 1><<<grid, 256, SMEM1>>>(hsh, hsh, cwh, cwh, compP,
                                             MROWS, CC, 65536, 65536, 65536 / SPLITK, thr);
        compress_epilogue_kernel<<<(MROWS * CC) / 256, 256>>>(cb, thr);
    }

    // gating
    g_gate_kernel<<<MROWS, 32>>>(gsim, ggates, thr);
    f_gate_kernel<<<MT / 8, 256>>>(hs, fsim, fgates);

    // QKV GEMM (split-bf16 3-term): (16384 x 1024) @ (1024 x 3072)
    {
        dim3 grid(3072 / 128, MT / 128, 1);
        gemm_mma<0, 3><<<grid, 256, SMEM3>>>(hsh, hsl, wqh, wql, qkv,
                                             MT, 3072, 1024, 1024, 1024, nullptr);
    }

    // RoPE on q,k
    rope_kernel<<<(2 * MT * EE * 32) / 256, 256>>>(pos);

    // attention (rw folded in, writes wctx hi/lo)
    attn_kernel<<<BB * EE * NBLK * 2, 256>>>();

    // output GEMM (split-bf16 3-term): (16384 x 1024) @ (1024 x 1024) -> d_out
    {
        dim3 grid(1024 / 128, MT / 128, 1);
        gemm_mma<0, 3><<<grid, 256, SMEM3>>>(wch, wcl, oth, otl, out,
                                             MT, 1024, 1024, 1024, 1024, nullptr);
    }
}